// round 13
// baseline (speedup 1.0000x reference)
#include <cuda_runtime.h>
#include <math.h>
#include <cstdint>

#define NN     100000
#define EE_MAX 3400000
#define HD     16
#define FIN    767
#define NC     10
#define EPSV   1e-12f

// ---------------- scratch ---------------------------------------------------
__device__ float g_hn  [NN * HD];   // normalized h
__device__ float g_nrm1[NN];        // max(||h||, eps)
__device__ float g_x1n [NN * HD];   // normalized x1
__device__ float g_nrm2[NN];        // max(||x1||, eps)
__device__ int   g_deg [NN];
__device__ int   g_rowptr[NN + 1];
__device__ int   g_cursor[NN];
__device__ int   g_csrc[EE_MAX];
__device__ int   g_aux[256];

// ---------------- CSR build (int2 = measured best) ---------------------------
__global__ void k_count(const int* __restrict__ ei, int E, int n) {
    int idx = blockIdx.x * blockDim.x + threadIdx.x;
    int half = E >> 1;
    if (idx < half) {
        int2 d = __ldg((const int2*)(ei + E) + idx);
        atomicAdd(&g_deg[d.x], 1);
        atomicAdd(&g_deg[d.y], 1);
    } else if (idx < half + n) {
        atomicAdd(&g_deg[idx - half], 1);
    }
}

__global__ void k_scan_chunk(int n) {
    __shared__ int wsums[16];
    int tid = threadIdx.x, lane = tid & 31, w = tid >> 5;
    int gid = blockIdx.x * 512 + tid;
    int v = (gid < n) ? g_deg[gid] : 0;
    int s = v;
#pragma unroll
    for (int off = 1; off < 32; off <<= 1) {
        int t = __shfl_up_sync(0xffffffffu, s, off);
        if (lane >= off) s += t;
    }
    if (lane == 31) wsums[w] = s;
    __syncthreads();
    int add = 0;
#pragma unroll
    for (int i = 0; i < 16; i++) add += (i < w) ? wsums[i] : 0;
    s += add;
    if (gid < n) g_rowptr[gid + 1] = s;
    if (tid == 511) g_aux[blockIdx.x] = s;
}

__global__ __launch_bounds__(512) void k_scan_add(int n, int nchunk) {
    __shared__ int wsum[16];
    int tid = threadIdx.x, lane = tid & 31, w = tid >> 5;
    int b = blockIdx.x;
    int v = (tid < b && tid < nchunk) ? g_aux[tid] : 0;
#pragma unroll
    for (int off = 16; off; off >>= 1) v += __shfl_xor_sync(0xffffffffu, v, off);
    if (lane == 0) wsum[w] = v;
    __syncthreads();
    if (w == 0) {
        int t = (lane < 16) ? wsum[lane] : 0;
#pragma unroll
        for (int off = 8; off; off >>= 1) t += __shfl_xor_sync(0xffffffffu, t, off);
        if (lane == 0) wsum[0] = t;
    }
    __syncthreads();
    int offset = wsum[0];

    int gid = b * 512 + tid;
    if (gid < n) {
        int r = g_rowptr[gid + 1] + offset;
        g_rowptr[gid + 1] = r;
        if (gid + 1 < n) g_cursor[gid + 1] = r;
    }
    if (gid == 0) { g_rowptr[0] = 0; g_cursor[0] = 0; }
}

__global__ void k_scatter(const int* __restrict__ ei, int E, int n) {
    int idx = blockIdx.x * blockDim.x + threadIdx.x;
    int half = E >> 1;
    if (idx < half) {
        int2 s = __ldg((const int2*)ei + idx);
        int2 d = __ldg((const int2*)(ei + E) + idx);
        int p0 = atomicAdd(&g_cursor[d.x], 1);
        g_csrc[p0] = s.x;
        int p1 = atomicAdd(&g_cursor[d.y], 1);
        g_csrc[p1] = s.y;
    } else if (idx < half + n) {
        int v = idx - half;
        int pos = atomicAdd(&g_cursor[v], 1);
        g_csrc[pos] = v;
    }
}

// ---------------- lin1 via mma.sync (HMMA bf16, 3-product hi/lo split) -------
// Block = 128 rows (8 warps x 16-row tiles). K in 24 chunks of 32.
// W staged once (bf16x2 k-pairs, u32 stride 388 -> conflict-free B frags).
// x staged per chunk pre-split hi/lo (u32 stride 20 -> conflict-free A frags).
#define W_STRIDE 388
#define A_STRIDE 20
#define OFF_WHI  0
#define OFF_WLO  (16 * W_STRIDE)                 // u32 offsets
#define OFF_AHI  (2 * 16 * W_STRIDE)
#define OFF_ALO  (2 * 16 * W_STRIDE + 128 * A_STRIDE)
#define LIN1_SMEM_BYTES ((2 * 16 * W_STRIDE + 2 * 128 * A_STRIDE) * 4)  // 70144

__device__ __forceinline__ void split_pack(float v0, float v1,
                                           uint32_t& hp, uint32_t& lp) {
    // hp = {hi: bf16(v1), lo: bf16(v0)}
    asm("cvt.rn.bf16x2.f32 %0, %1, %2;" : "=r"(hp) : "f"(v1), "f"(v0));
    float h0 = __uint_as_float(hp << 16);
    float h1 = __uint_as_float(hp & 0xFFFF0000u);
    float l0 = v0 - h0, l1 = v1 - h1;
    asm("cvt.rn.bf16x2.f32 %0, %1, %2;" : "=r"(lp) : "f"(l1), "f"(l0));
}

__device__ __forceinline__ void mma_bf16(float* c, const uint32_t* a,
                                         uint32_t b0, uint32_t b1) {
    asm volatile(
        "mma.sync.aligned.m16n8k16.row.col.f32.bf16.bf16.f32 "
        "{%0,%1,%2,%3}, {%4,%5,%6,%7}, {%8,%9}, {%0,%1,%2,%3};"
        : "+f"(c[0]), "+f"(c[1]), "+f"(c[2]), "+f"(c[3])
        : "r"(a[0]), "r"(a[1]), "r"(a[2]), "r"(a[3]), "r"(b0), "r"(b1));
}

__global__ __launch_bounds__(256) void k_lin1_mma(const float* __restrict__ x,
                                                  const float* __restrict__ w,
                                                  const float* __restrict__ b,
                                                  float* __restrict__ hn,
                                                  float* __restrict__ nrm,
                                                  int n) {
    extern __shared__ uint32_t sm[];
    uint32_t* whi = sm + OFF_WHI;
    uint32_t* wlo = sm + OFF_WLO;
    uint32_t* ahi = sm + OFF_AHI;
    uint32_t* alo = sm + OFF_ALO;

    int tid = threadIdx.x;
    int warp = tid >> 5, lane = tid & 31;
    int g = lane >> 2, t = lane & 3;
    int rowBase = blockIdx.x * 128;

    // ---- stage W (16 rows x 384 k-pairs) once ----
    for (int p = tid; p < 16 * 384; p += 256) {
        int row = p / 384;
        int cp  = p - row * 384;
        int k   = 2 * cp;
        float v0 = (k < FIN)     ? __ldg(w + row * FIN + k)     : 0.f;
        float v1 = (k + 1 < FIN) ? __ldg(w + row * FIN + k + 1) : 0.f;
        uint32_t hp, lp;
        split_pack(v0, v1, hp, lp);
        whi[row * W_STRIDE + cp] = hp;
        wlo[row * W_STRIDE + cp] = lp;
    }
    __syncthreads();

    float cn0[4] = {0.f, 0.f, 0.f, 0.f};   // n in [0,8)
    float cn1[4] = {0.f, 0.f, 0.f, 0.f};   // n in [8,16)
    int wr16 = warp * 16;

    for (int c = 0; c < 24; ++c) {
        int kc = c * 32;                    // chunk base (k), 16 pairs
        // ---- stage A chunk: 128 rows x 16 pairs ----
        for (int p = tid; p < 128 * 16; p += 256) {
            int row = p >> 4, cp = p & 15;
            int k = kc + 2 * cp;
            int gr = rowBase + row;
            float v0 = 0.f, v1 = 0.f;
            if (gr < n) {
                const float* xr = x + (size_t)gr * FIN;
                if (k < FIN)     v0 = __ldg(xr + k);
                if (k + 1 < FIN) v1 = __ldg(xr + k + 1);
            }
            uint32_t hp, lp;
            split_pack(v0, v1, hp, lp);
            ahi[row * A_STRIDE + cp] = hp;
            alo[row * A_STRIDE + cp] = lp;
        }
        __syncthreads();

        // ---- 2 k-steps of 16 ----
#pragma unroll
        for (int ks = 0; ks < 2; ++ks) {
            int colA = ks * 8 + t;             // pair index within chunk
            int rgA = (wr16 + g) * A_STRIDE;
            int rgB = (wr16 + g + 8) * A_STRIDE;
            uint32_t ah[4], al[4];
            ah[0] = ahi[rgA + colA];     ah[1] = ahi[rgB + colA];
            ah[2] = ahi[rgA + colA + 4]; ah[3] = ahi[rgB + colA + 4];
            al[0] = alo[rgA + colA];     al[1] = alo[rgB + colA];
            al[2] = alo[rgA + colA + 4]; al[3] = alo[rgB + colA + 4];

            int wcol = c * 16 + ks * 8 + t;    // global pair index
            uint32_t bh0  = whi[g * W_STRIDE + wcol];
            uint32_t bh1  = whi[g * W_STRIDE + wcol + 4];
            uint32_t bl0  = wlo[g * W_STRIDE + wcol];
            uint32_t bl1  = wlo[g * W_STRIDE + wcol + 4];
            uint32_t bh0n = whi[(g + 8) * W_STRIDE + wcol];
            uint32_t bh1n = whi[(g + 8) * W_STRIDE + wcol + 4];
            uint32_t bl0n = wlo[(g + 8) * W_STRIDE + wcol];
            uint32_t bl1n = wlo[(g + 8) * W_STRIDE + wcol + 4];

            mma_bf16(cn0, ah, bh0, bh1);   // hi*hi
            mma_bf16(cn0, ah, bl0, bl1);   // hi*lo
            mma_bf16(cn0, al, bh0, bh1);   // lo*hi
            mma_bf16(cn1, ah, bh0n, bh1n);
            mma_bf16(cn1, ah, bl0n, bl1n);
            mma_bf16(cn1, al, bh0n, bh1n);
        }
        __syncthreads();
    }

    // ---- epilogue: bias + relu + row-normalize ----
    float b0v = __ldg(b + 2 * t),     b1v = __ldg(b + 2 * t + 1);
    float b2v = __ldg(b + 2 * t + 8), b3v = __ldg(b + 2 * t + 9);

    // row A = rowBase + wr16 + g  (c0,c1 of each half)
    {
        int rA = rowBase + wr16 + g;
        float h0 = fmaxf(cn0[0] + b0v, 0.f);
        float h1 = fmaxf(cn0[1] + b1v, 0.f);
        float h2 = fmaxf(cn1[0] + b2v, 0.f);
        float h3 = fmaxf(cn1[1] + b3v, 0.f);
        float ss = h0*h0 + h1*h1 + h2*h2 + h3*h3;
        ss += __shfl_xor_sync(0xffffffffu, ss, 1);
        ss += __shfl_xor_sync(0xffffffffu, ss, 2);
        float nr = fmaxf(sqrtf(ss), EPSV);
        float iv = 1.f / nr;
        if (rA < n) {
            float* o = hn + (size_t)rA * HD;
            *(float2*)(o + 2 * t)     = make_float2(h0 * iv, h1 * iv);
            *(float2*)(o + 2 * t + 8) = make_float2(h2 * iv, h3 * iv);
            if (t == 0) nrm[rA] = nr;
        }
    }
    // row B = rowA + 8  (c2,c3 of each half)
    {
        int rB = rowBase + wr16 + g + 8;
        float h0 = fmaxf(cn0[2] + b0v, 0.f);
        float h1 = fmaxf(cn0[3] + b1v, 0.f);
        float h2 = fmaxf(cn1[2] + b2v, 0.f);
        float h3 = fmaxf(cn1[3] + b3v, 0.f);
        float ss = h0*h0 + h1*h1 + h2*h2 + h3*h3;
        ss += __shfl_xor_sync(0xffffffffu, ss, 1);
        ss += __shfl_xor_sync(0xffffffffu, ss, 2);
        float nr = fmaxf(sqrtf(ss), EPSV);
        float iv = 1.f / nr;
        if (rB < n) {
            float* o = hn + (size_t)rB * HD;
            *(float2*)(o + 2 * t)     = make_float2(h0 * iv, h1 * iv);
            *(float2*)(o + 2 * t + 8) = make_float2(h2 * iv, h3 * iv);
            if (t == 0) nrm[rB] = nr;
        }
    }
}

// ---------------- AGNN conv: compile-time bases + __ldg + clamped loads ------
template <int MODE>
__global__ __launch_bounds__(256) void k_conv(const float* __restrict__ beta_ptr,
                                              float* __restrict__ out,
                                              const float* __restrict__ w2,
                                              const float* __restrict__ b2,
                                              int n) {
    __shared__ float ws[NC * HD + NC];
    if (MODE == 1) {
        if (threadIdx.x < NC * HD) ws[threadIdx.x] = w2[threadIdx.x];
        if (threadIdx.x < NC)      ws[NC * HD + threadIdx.x] = b2[threadIdx.x];
        __syncthreads();
    }

    const float4* fn4  = (const float4*)(MODE == 0 ? g_hn : g_x1n);
    const float*  nrmT = (MODE == 0 ? g_nrm1 : g_nrm2);

    int gw    = (blockIdx.x * blockDim.x + threadIdx.x) >> 5;
    int lane  = threadIdx.x & 31;
    if (gw >= n) return;
    int chunk = lane & 3;
    int slot  = lane >> 2;

    float beta = (MODE == 1) ? __ldg(beta_ptr) : 1.0f;
    float ab   = fabsf(beta);

    float4 q = __ldg(fn4 + gw * 4 + chunk);
    q.x *= beta; q.y *= beta; q.z *= beta; q.w *= beta;

    int start = __ldg(&g_rowptr[gw]), end = __ldg(&g_rowptr[gw + 1]);
    int last  = end - 1;
    int nit = (end - start + 15) >> 4;

    float ssum = 0.f;
    float4 acc = make_float4(0.f, 0.f, 0.f, 0.f);

    int e0 = start + slot;
    bool v0 = (e0 < end),  v1 = (e0 + 8 < end);
    int s0 = __ldg(&g_csrc[min(e0, last)]);
    int s1 = __ldg(&g_csrc[min(e0 + 8, last)]);

    for (int it = 0; it < nit; ++it) {
        int  e2 = e0 + 16;
        bool v2 = (e2 < end), v3 = (e2 + 8 < end);
        int  s2 = __ldg(&g_csrc[min(e2, last)]);
        int  s3 = __ldg(&g_csrc[min(e2 + 8, last)]);
        float nv0 = __ldg(&nrmT[s0]);
        float nv1 = __ldg(&nrmT[s1]);
        float4 f0 = __ldg(fn4 + s0 * 4 + chunk);
        float4 f1 = __ldg(fn4 + s1 * 4 + chunk);
        float d0 = f0.x*q.x + f0.y*q.y + f0.z*q.z + f0.w*q.w;
        float d1 = f1.x*q.x + f1.y*q.y + f1.z*q.z + f1.w*q.w;
        d0 += __shfl_xor_sync(0xffffffffu, d0, 1);
        d1 += __shfl_xor_sync(0xffffffffu, d1, 1);
        d0 += __shfl_xor_sync(0xffffffffu, d0, 2);
        d1 += __shfl_xor_sync(0xffffffffu, d1, 2);
        float ex0 = v0 ? __expf(d0 - ab) : 0.f;
        float ex1 = v1 ? __expf(d1 - ab) : 0.f;
        float w0 = ex0 * nv0, w1 = ex1 * nv1;
        ssum += ex0 + ex1;
        acc.x += w0 * f0.x + w1 * f1.x;
        acc.y += w0 * f0.y + w1 * f1.y;
        acc.z += w0 * f0.z + w1 * f1.z;
        acc.w += w0 * f0.w + w1 * f1.w;
        e0 = e2; s0 = s2; s1 = s3; v0 = v2; v1 = v3;
    }

#pragma unroll
    for (int off = 4; off <= 16; off <<= 1) {
        ssum  += __shfl_xor_sync(0xffffffffu, ssum,  off);
        acc.x += __shfl_xor_sync(0xffffffffu, acc.x, off);
        acc.y += __shfl_xor_sync(0xffffffffu, acc.y, off);
        acc.z += __shfl_xor_sync(0xffffffffu, acc.z, off);
        acc.w += __shfl_xor_sync(0xffffffffu, acc.w, off);
    }
    float inv = 1.f / ssum;
    float4 o = make_float4(acc.x*inv, acc.y*inv, acc.z*inv, acc.w*inv);

    if (MODE == 0) {
        float ss = o.x*o.x + o.y*o.y + o.z*o.z + o.w*o.w;
        ss += __shfl_xor_sync(0xffffffffu, ss, 1);
        ss += __shfl_xor_sync(0xffffffffu, ss, 2);
        float nr   = fmaxf(sqrtf(ss), EPSV);
        float invn = 1.f / nr;
        if (slot == 0) {
            ((float4*)out)[gw * 4 + chunk] = o;
            ((float4*)g_x1n)[gw * 4 + chunk] =
                make_float4(o.x*invn, o.y*invn, o.z*invn, o.w*invn);
            if (lane == 0) g_nrm2[gw] = nr;
        }
    } else {
        float z[NC];
#pragma unroll
        for (int c = 0; c < NC; c++) {
            const float* wc = ws + c * HD + chunk * 4;
            z[c] = o.x*wc[0] + o.y*wc[1] + o.z*wc[2] + o.w*wc[3];
        }
#pragma unroll
        for (int off = 1; off <= 2; off <<= 1)
#pragma unroll
            for (int c = 0; c < NC; c++)
                z[c] += __shfl_xor_sync(0xffffffffu, z[c], off);
#pragma unroll
        for (int c = 0; c < NC; c++) z[c] += ws[NC * HD + c];
        float mx = z[0];
#pragma unroll
        for (int c = 1; c < NC; c++) mx = fmaxf(mx, z[c]);
        float se = 0.f;
#pragma unroll
        for (int c = 0; c < NC; c++) se += __expf(z[c] - mx);
        float lse = mx + __logf(se);
        if (lane < NC) out[gw * NC + lane] = z[lane] - lse;
    }
}

// ---------------- launch -----------------------------------------------------
extern "C" void kernel_launch(void* const* d_in, const int* in_sizes, int n_in,
                              void* d_out, int out_size) {
    const float* x    = (const float*)d_in[0];
    const int*   ei   = (const int*)  d_in[1];
    const float* w1   = (const float*)d_in[2];
    const float* b1   = (const float*)d_in[3];
    const float* bet2 = (const float*)d_in[4];
    const float* w2   = (const float*)d_in[5];
    const float* b2   = (const float*)d_in[6];
    float* out = (float*)d_out;

    int n = NN;
    int E = in_sizes[1] / 2;

    float* x1 = out + (size_t)n * NC;   // x1 output lives in d_out tail

    float* p_hn;  cudaGetSymbolAddress((void**)&p_hn,  g_hn);
    float* p_n1;  cudaGetSymbolAddress((void**)&p_n1,  g_nrm1);
    int*   p_deg; cudaGetSymbolAddress((void**)&p_deg, g_deg);

    static cudaStream_t sMain = nullptr, s2 = nullptr;
    static cudaEvent_t evFork = nullptr, evJoinA = nullptr, evJoinB = nullptr;
    if (!s2) {
        int loPri, hiPri;
        cudaDeviceGetStreamPriorityRange(&loPri, &hiPri);
        cudaStreamCreateWithPriority(&sMain, cudaStreamNonBlocking, hiPri);
        cudaStreamCreateWithPriority(&s2,    cudaStreamNonBlocking, loPri);
        cudaEventCreateWithFlags(&evFork,  cudaEventDisableTiming);
        cudaEventCreateWithFlags(&evJoinA, cudaEventDisableTiming);
        cudaEventCreateWithFlags(&evJoinB, cudaEventDisableTiming);
        cudaFuncSetAttribute(k_lin1_mma,
                             cudaFuncAttributeMaxDynamicSharedMemorySize,
                             LIN1_SMEM_BYTES);
    }

    const int T = 256;
    int nchunk = (n + 511) / 512;
    int half = E >> 1;

    // ---- fork: CSR build on s2 (low pri), lin1 on sMain (high pri) ----
    cudaEventRecord(evFork, 0);
    cudaStreamWaitEvent(s2, evFork, 0);
    cudaStreamWaitEvent(sMain, evFork, 0);

    cudaMemsetAsync(p_deg, 0, n * sizeof(int), s2);
    // kernel #1
    k_count<<<(half + n + T - 1) / T, T, 0, s2>>>(ei, E, n);
    // kernel #2
    k_scan_chunk<<<nchunk, 512, 0, s2>>>(n);
    // kernel #3
    k_scan_add<<<nchunk, 512, 0, s2>>>(n, nchunk);

    // kernel #4 (PROFILED): lin1 via HMMA
    k_lin1_mma<<<(n + 127) / 128, 256, LIN1_SMEM_BYTES, sMain>>>(
        x, w1, b1, p_hn, p_n1, n);

    // kernel #5: scatter
    k_scatter<<<(half + n + T - 1) / T, T, 0, s2>>>(ei, E, n);

    // ---- join back onto capture stream ----
    cudaEventRecord(evJoinA, s2);
    cudaEventRecord(evJoinB, sMain);
    cudaStreamWaitEvent(0, evJoinA, 0);
    cudaStreamWaitEvent(0, evJoinB, 0);

    int convBlocks = (n * 32 + 255) / 256;
    // kernel #6: conv1
    k_conv<0><<<convBlocks, 256>>>(nullptr, x1, nullptr, nullptr, n);
    // kernel #7: conv2 (+ fused lin2/log_softmax)
    k_conv<1><<<convBlocks, 256>>>(bet2, out, w2, b2, n);
}

// round 14
// speedup vs baseline: 1.2332x; 1.2332x over previous
#include <cuda_runtime.h>
#include <math.h>
#include <cstdint>

#define NN     100000
#define EE_MAX 3400000
#define HD     16
#define FIN    767
#define NC     10
#define EPSV   1e-12f

// ---------------- scratch ---------------------------------------------------
__device__ float g_hn  [NN * HD];   // normalized h
__device__ float g_nrm1[NN];        // max(||h||, eps)
__device__ float g_x1n [NN * HD];   // normalized x1
__device__ float g_nrm2[NN];        // max(||x1||, eps)
__device__ int   g_deg [NN];
__device__ int   g_rowptr[NN + 1];
__device__ int   g_cursor[NN];
__device__ int   g_csrc[EE_MAX];
__device__ int   g_aux[256];

// ---------------- CSR build (int2 = measured best) ---------------------------
__global__ void k_count(const int* __restrict__ ei, int E, int n) {
    int idx = blockIdx.x * blockDim.x + threadIdx.x;
    int half = E >> 1;
    if (idx < half) {
        int2 d = __ldg((const int2*)(ei + E) + idx);
        atomicAdd(&g_deg[d.x], 1);
        atomicAdd(&g_deg[d.y], 1);
    } else if (idx < half + n) {
        atomicAdd(&g_deg[idx - half], 1);
    }
}

__global__ void k_scan_chunk(int n) {
    __shared__ int wsums[16];
    int tid = threadIdx.x, lane = tid & 31, w = tid >> 5;
    int gid = blockIdx.x * 512 + tid;
    int v = (gid < n) ? g_deg[gid] : 0;
    int s = v;
#pragma unroll
    for (int off = 1; off < 32; off <<= 1) {
        int t = __shfl_up_sync(0xffffffffu, s, off);
        if (lane >= off) s += t;
    }
    if (lane == 31) wsums[w] = s;
    __syncthreads();
    int add = 0;
#pragma unroll
    for (int i = 0; i < 16; i++) add += (i < w) ? wsums[i] : 0;
    s += add;
    if (gid < n) g_rowptr[gid + 1] = s;
    if (tid == 511) g_aux[blockIdx.x] = s;
}

__global__ __launch_bounds__(512) void k_scan_add(int n, int nchunk) {
    __shared__ int wsum[16];
    int tid = threadIdx.x, lane = tid & 31, w = tid >> 5;
    int b = blockIdx.x;
    int v = (tid < b && tid < nchunk) ? g_aux[tid] : 0;
#pragma unroll
    for (int off = 16; off; off >>= 1) v += __shfl_xor_sync(0xffffffffu, v, off);
    if (lane == 0) wsum[w] = v;
    __syncthreads();
    if (w == 0) {
        int t = (lane < 16) ? wsum[lane] : 0;
#pragma unroll
        for (int off = 8; off; off >>= 1) t += __shfl_xor_sync(0xffffffffu, t, off);
        if (lane == 0) wsum[0] = t;
    }
    __syncthreads();
    int offset = wsum[0];

    int gid = b * 512 + tid;
    if (gid < n) {
        int r = g_rowptr[gid + 1] + offset;
        g_rowptr[gid + 1] = r;
        if (gid + 1 < n) g_cursor[gid + 1] = r;
    }
    if (gid == 0) { g_rowptr[0] = 0; g_cursor[0] = 0; }
}

__global__ void k_scatter(const int* __restrict__ ei, int E, int n) {
    int idx = blockIdx.x * blockDim.x + threadIdx.x;
    int half = E >> 1;
    if (idx < half) {
        int2 s = __ldg((const int2*)ei + idx);
        int2 d = __ldg((const int2*)(ei + E) + idx);
        int p0 = atomicAdd(&g_cursor[d.x], 1);
        g_csrc[p0] = s.x;
        int p1 = atomicAdd(&g_cursor[d.y], 1);
        g_csrc[p1] = s.y;
    } else if (idx < half + n) {
        int v = idx - half;
        int pos = atomicAdd(&g_cursor[v], 1);
        g_csrc[pos] = v;
    }
}

// ---------------- lin1 via mma.sync: A direct-from-global, no k-loop barriers
// Block = 128 rows (8 warps x 16-row tiles). 48 k-steps of 16.
// W staged once in smem (bf16x2 k-pairs, u32 stride 388 -> conflict-free LDS).
// A fragments loaded per-thread straight from x, hi/lo split in registers.
#define W_STRIDE 388
#define LIN1_SMEM_BYTES (2 * 16 * W_STRIDE * 4)   // 49664

__device__ __forceinline__ void split_pack(float v0, float v1,
                                           uint32_t& hp, uint32_t& lp) {
    // hp = {hi: bf16(v1), lo: bf16(v0)}
    asm("cvt.rn.bf16x2.f32 %0, %1, %2;" : "=r"(hp) : "f"(v1), "f"(v0));
    float h0 = __uint_as_float(hp << 16);
    float h1 = __uint_as_float(hp & 0xFFFF0000u);
    float l0 = v0 - h0, l1 = v1 - h1;
    asm("cvt.rn.bf16x2.f32 %0, %1, %2;" : "=r"(lp) : "f"(l1), "f"(l0));
}

__device__ __forceinline__ void mma_bf16(float* c, const uint32_t* a,
                                         uint32_t b0, uint32_t b1) {
    asm volatile(
        "mma.sync.aligned.m16n8k16.row.col.f32.bf16.bf16.f32 "
        "{%0,%1,%2,%3}, {%4,%5,%6,%7}, {%8,%9}, {%0,%1,%2,%3};"
        : "+f"(c[0]), "+f"(c[1]), "+f"(c[2]), "+f"(c[3])
        : "r"(a[0]), "r"(a[1]), "r"(a[2]), "r"(a[3]), "r"(b0), "r"(b1));
}

__global__ __launch_bounds__(256) void k_lin1_mma(const float* __restrict__ x,
                                                  const float* __restrict__ w,
                                                  const float* __restrict__ b,
                                                  float* __restrict__ hn,
                                                  float* __restrict__ nrm,
                                                  int n) {
    extern __shared__ uint32_t sm[];
    uint32_t* whi = sm;
    uint32_t* wlo = sm + 16 * W_STRIDE;

    int tid = threadIdx.x;
    int warp = tid >> 5, lane = tid & 31;
    int g = lane >> 2, t = lane & 3;
    int rowBase = blockIdx.x * 128;

    // ---- stage W (16 rows x 384 k-pairs) once ----
    for (int p = tid; p < 16 * 384; p += 256) {
        int row = p / 384;
        int cp  = p - row * 384;
        int k   = 2 * cp;
        float v0 = (k < FIN)     ? __ldg(w + row * FIN + k)     : 0.f;
        float v1 = (k + 1 < FIN) ? __ldg(w + row * FIN + k + 1) : 0.f;
        uint32_t hp, lp;
        split_pack(v0, v1, hp, lp);
        whi[row * W_STRIDE + cp] = hp;
        wlo[row * W_STRIDE + cp] = lp;
    }
    __syncthreads();

    float cn0[4] = {0.f, 0.f, 0.f, 0.f};   // n in [0,8)
    float cn1[4] = {0.f, 0.f, 0.f, 0.f};   // n in [8,16)

    int rA = rowBase + warp * 16 + g;       // rows for c0/c1
    int rB = rA + 8;                        // rows for c2/c3
    bool okA = (rA < n), okB = (rB < n);
    const float* xA = x + (size_t)(okA ? rA : 0) * FIN;
    const float* xB = x + (size_t)(okB ? rB : 0) * FIN;
    const uint32_t* w0h = whi + g * W_STRIDE;
    const uint32_t* w0l = wlo + g * W_STRIDE;
    const uint32_t* w1h = whi + (g + 8) * W_STRIDE;
    const uint32_t* w1l = wlo + (g + 8) * W_STRIDE;

#pragma unroll 2
    for (int ks = 0; ks < 48; ++ks) {
        int cp0 = ks * 8 + t;               // pair index (first quad)
        int cp1 = cp0 + 4;                  // second quad
        int k0 = 2 * cp0, k1 = 2 * cp1;
        // last pair (cp1==383) has float 767 OOB -> 0 (weight slot is 0 anyway)
        bool hi1ok = (k1 + 1 < FIN);

        float a0 = okA ? __ldg(xA + k0)     : 0.f;
        float a1 = okA ? __ldg(xA + k0 + 1) : 0.f;
        float a2 = okA ? (hi1ok ? __ldg(xA + k1 + 1) : 0.f) : 0.f;
        float a2l= okA ? __ldg(xA + k1)     : 0.f;
        float b0f= okB ? __ldg(xB + k0)     : 0.f;
        float b1f= okB ? __ldg(xB + k0 + 1) : 0.f;
        float b2l= okB ? __ldg(xB + k1)     : 0.f;
        float b2 = okB ? (hi1ok ? __ldg(xB + k1 + 1) : 0.f) : 0.f;

        uint32_t ah[4], al[4];
        split_pack(a0,  a1, ah[0], al[0]);   // row A, quad 0
        split_pack(b0f, b1f, ah[1], al[1]);  // row B, quad 0
        split_pack(a2l, a2, ah[2], al[2]);   // row A, quad 1
        split_pack(b2l, b2, ah[3], al[3]);   // row B, quad 1

        uint32_t bh0  = w0h[cp0], bh1  = w0h[cp1];
        uint32_t bl0  = w0l[cp0], bl1  = w0l[cp1];
        uint32_t bh0n = w1h[cp0], bh1n = w1h[cp1];
        uint32_t bl0n = w1l[cp0], bl1n = w1l[cp1];

        mma_bf16(cn0, ah, bh0, bh1);   // hi*hi
        mma_bf16(cn0, ah, bl0, bl1);   // hi*lo
        mma_bf16(cn0, al, bh0, bh1);   // lo*hi
        mma_bf16(cn1, ah, bh0n, bh1n);
        mma_bf16(cn1, ah, bl0n, bl1n);
        mma_bf16(cn1, al, bh0n, bh1n);
    }

    // ---- epilogue: bias + relu + row-normalize (verified in R13) ----
    float b0v = __ldg(b + 2 * t),     b1v = __ldg(b + 2 * t + 1);
    float b2v = __ldg(b + 2 * t + 8), b3v = __ldg(b + 2 * t + 9);

    {
        float h0 = fmaxf(cn0[0] + b0v, 0.f);
        float h1 = fmaxf(cn0[1] + b1v, 0.f);
        float h2 = fmaxf(cn1[0] + b2v, 0.f);
        float h3 = fmaxf(cn1[1] + b3v, 0.f);
        float ss = h0*h0 + h1*h1 + h2*h2 + h3*h3;
        ss += __shfl_xor_sync(0xffffffffu, ss, 1);
        ss += __shfl_xor_sync(0xffffffffu, ss, 2);
        float nr = fmaxf(sqrtf(ss), EPSV);
        float iv = 1.f / nr;
        if (okA) {
            float* o = hn + (size_t)rA * HD;
            *(float2*)(o + 2 * t)     = make_float2(h0 * iv, h1 * iv);
            *(float2*)(o + 2 * t + 8) = make_float2(h2 * iv, h3 * iv);
            if (t == 0) nrm[rA] = nr;
        }
    }
    {
        float h0 = fmaxf(cn0[2] + b0v, 0.f);
        float h1 = fmaxf(cn0[3] + b1v, 0.f);
        float h2 = fmaxf(cn1[2] + b2v, 0.f);
        float h3 = fmaxf(cn1[3] + b3v, 0.f);
        float ss = h0*h0 + h1*h1 + h2*h2 + h3*h3;
        ss += __shfl_xor_sync(0xffffffffu, ss, 1);
        ss += __shfl_xor_sync(0xffffffffu, ss, 2);
        float nr = fmaxf(sqrtf(ss), EPSV);
        float iv = 1.f / nr;
        if (okB) {
            float* o = hn + (size_t)rB * HD;
            *(float2*)(o + 2 * t)     = make_float2(h0 * iv, h1 * iv);
            *(float2*)(o + 2 * t + 8) = make_float2(h2 * iv, h3 * iv);
            if (t == 0) nrm[rB] = nr;
        }
    }
}

// ---------------- AGNN conv: compile-time bases + __ldg + clamped loads ------
template <int MODE>
__global__ __launch_bounds__(256) void k_conv(const float* __restrict__ beta_ptr,
                                              float* __restrict__ out,
                                              const float* __restrict__ w2,
                                              const float* __restrict__ b2,
                                              int n) {
    __shared__ float ws[NC * HD + NC];
    if (MODE == 1) {
        if (threadIdx.x < NC * HD) ws[threadIdx.x] = w2[threadIdx.x];
        if (threadIdx.x < NC)      ws[NC * HD + threadIdx.x] = b2[threadIdx.x];
        __syncthreads();
    }

    const float4* fn4  = (const float4*)(MODE == 0 ? g_hn : g_x1n);
    const float*  nrmT = (MODE == 0 ? g_nrm1 : g_nrm2);

    int gw    = (blockIdx.x * blockDim.x + threadIdx.x) >> 5;
    int lane  = threadIdx.x & 31;
    if (gw >= n) return;
    int chunk = lane & 3;
    int slot  = lane >> 2;

    float beta = (MODE == 1) ? __ldg(beta_ptr) : 1.0f;
    float ab   = fabsf(beta);

    float4 q = __ldg(fn4 + gw * 4 + chunk);
    q.x *= beta; q.y *= beta; q.z *= beta; q.w *= beta;

    int start = __ldg(&g_rowptr[gw]), end = __ldg(&g_rowptr[gw + 1]);
    int last  = end - 1;
    int nit = (end - start + 15) >> 4;

    float ssum = 0.f;
    float4 acc = make_float4(0.f, 0.f, 0.f, 0.f);

    int e0 = start + slot;
    bool v0 = (e0 < end),  v1 = (e0 + 8 < end);
    int s0 = __ldg(&g_csrc[min(e0, last)]);
    int s1 = __ldg(&g_csrc[min(e0 + 8, last)]);

    for (int it = 0; it < nit; ++it) {
        int  e2 = e0 + 16;
        bool v2 = (e2 < end), v3 = (e2 + 8 < end);
        int  s2 = __ldg(&g_csrc[min(e2, last)]);
        int  s3 = __ldg(&g_csrc[min(e2 + 8, last)]);
        float nv0 = __ldg(&nrmT[s0]);
        float nv1 = __ldg(&nrmT[s1]);
        float4 f0 = __ldg(fn4 + s0 * 4 + chunk);
        float4 f1 = __ldg(fn4 + s1 * 4 + chunk);
        float d0 = f0.x*q.x + f0.y*q.y + f0.z*q.z + f0.w*q.w;
        float d1 = f1.x*q.x + f1.y*q.y + f1.z*q.z + f1.w*q.w;
        d0 += __shfl_xor_sync(0xffffffffu, d0, 1);
        d1 += __shfl_xor_sync(0xffffffffu, d1, 1);
        d0 += __shfl_xor_sync(0xffffffffu, d0, 2);
        d1 += __shfl_xor_sync(0xffffffffu, d1, 2);
        float ex0 = v0 ? __expf(d0 - ab) : 0.f;
        float ex1 = v1 ? __expf(d1 - ab) : 0.f;
        float w0 = ex0 * nv0, w1 = ex1 * nv1;
        ssum += ex0 + ex1;
        acc.x += w0 * f0.x + w1 * f1.x;
        acc.y += w0 * f0.y + w1 * f1.y;
        acc.z += w0 * f0.z + w1 * f1.z;
        acc.w += w0 * f0.w + w1 * f1.w;
        e0 = e2; s0 = s2; s1 = s3; v0 = v2; v1 = v3;
    }

#pragma unroll
    for (int off = 4; off <= 16; off <<= 1) {
        ssum  += __shfl_xor_sync(0xffffffffu, ssum,  off);
        acc.x += __shfl_xor_sync(0xffffffffu, acc.x, off);
        acc.y += __shfl_xor_sync(0xffffffffu, acc.y, off);
        acc.z += __shfl_xor_sync(0xffffffffu, acc.z, off);
        acc.w += __shfl_xor_sync(0xffffffffu, acc.w, off);
    }
    float inv = 1.f / ssum;
    float4 o = make_float4(acc.x*inv, acc.y*inv, acc.z*inv, acc.w*inv);

    if (MODE == 0) {
        float ss = o.x*o.x + o.y*o.y + o.z*o.z + o.w*o.w;
        ss += __shfl_xor_sync(0xffffffffu, ss, 1);
        ss += __shfl_xor_sync(0xffffffffu, ss, 2);
        float nr   = fmaxf(sqrtf(ss), EPSV);
        float invn = 1.f / nr;
        if (slot == 0) {
            ((float4*)out)[gw * 4 + chunk] = o;
            ((float4*)g_x1n)[gw * 4 + chunk] =
                make_float4(o.x*invn, o.y*invn, o.z*invn, o.w*invn);
            if (lane == 0) g_nrm2[gw] = nr;
        }
    } else {
        float z[NC];
#pragma unroll
        for (int c = 0; c < NC; c++) {
            const float* wc = ws + c * HD + chunk * 4;
            z[c] = o.x*wc[0] + o.y*wc[1] + o.z*wc[2] + o.w*wc[3];
        }
#pragma unroll
        for (int off = 1; off <= 2; off <<= 1)
#pragma unroll
            for (int c = 0; c < NC; c++)
                z[c] += __shfl_xor_sync(0xffffffffu, z[c], off);
#pragma unroll
        for (int c = 0; c < NC; c++) z[c] += ws[NC * HD + c];
        float mx = z[0];
#pragma unroll
        for (int c = 1; c < NC; c++) mx = fmaxf(mx, z[c]);
        float se = 0.f;
#pragma unroll
        for (int c = 0; c < NC; c++) se += __expf(z[c] - mx);
        float lse = mx + __logf(se);
        if (lane < NC) out[gw * NC + lane] = z[lane] - lse;
    }
}

// ---------------- launch -----------------------------------------------------
extern "C" void kernel_launch(void* const* d_in, const int* in_sizes, int n_in,
                              void* d_out, int out_size) {
    const float* x    = (const float*)d_in[0];
    const int*   ei   = (const int*)  d_in[1];
    const float* w1   = (const float*)d_in[2];
    const float* b1   = (const float*)d_in[3];
    const float* bet2 = (const float*)d_in[4];
    const float* w2   = (const float*)d_in[5];
    const float* b2   = (const float*)d_in[6];
    float* out = (float*)d_out;

    int n = NN;
    int E = in_sizes[1] / 2;

    float* x1 = out + (size_t)n * NC;   // x1 output lives in d_out tail

    float* p_hn;  cudaGetSymbolAddress((void**)&p_hn,  g_hn);
    float* p_n1;  cudaGetSymbolAddress((void**)&p_n1,  g_nrm1);
    int*   p_deg; cudaGetSymbolAddress((void**)&p_deg, g_deg);

    static cudaStream_t sMain = nullptr, s2 = nullptr;
    static cudaEvent_t evFork = nullptr, evJoinA = nullptr, evJoinB = nullptr;
    if (!s2) {
        int loPri, hiPri;
        cudaDeviceGetStreamPriorityRange(&loPri, &hiPri);
        cudaStreamCreateWithPriority(&sMain, cudaStreamNonBlocking, hiPri);
        cudaStreamCreateWithPriority(&s2,    cudaStreamNonBlocking, loPri);
        cudaEventCreateWithFlags(&evFork,  cudaEventDisableTiming);
        cudaEventCreateWithFlags(&evJoinA, cudaEventDisableTiming);
        cudaEventCreateWithFlags(&evJoinB, cudaEventDisableTiming);
        cudaFuncSetAttribute(k_lin1_mma,
                             cudaFuncAttributeMaxDynamicSharedMemorySize,
                             LIN1_SMEM_BYTES);
    }

    const int T = 256;
    int nchunk = (n + 511) / 512;
    int half = E >> 1;

    // ---- fork: CSR build on s2 (low pri), lin1 on sMain (high pri) ----
    cudaEventRecord(evFork, 0);
    cudaStreamWaitEvent(s2, evFork, 0);
    cudaStreamWaitEvent(sMain, evFork, 0);

    cudaMemsetAsync(p_deg, 0, n * sizeof(int), s2);
    // kernel #1
    k_count<<<(half + n + T - 1) / T, T, 0, s2>>>(ei, E, n);
    // kernel #2
    k_scan_chunk<<<nchunk, 512, 0, s2>>>(n);
    // kernel #3
    k_scan_add<<<nchunk, 512, 0, s2>>>(n, nchunk);

    // kernel #4 (PROFILED): lin1 via HMMA, A direct-from-global
    k_lin1_mma<<<(n + 127) / 128, 256, LIN1_SMEM_BYTES, sMain>>>(
        x, w1, b1, p_hn, p_n1, n);

    // kernel #5: scatter
    k_scatter<<<(half + n + T - 1) / T, T, 0, s2>>>(ei, E, n);

    // ---- join back onto capture stream ----
    cudaEventRecord(evJoinA, s2);
    cudaEventRecord(evJoinB, sMain);
    cudaStreamWaitEvent(0, evJoinA, 0);
    cudaStreamWaitEvent(0, evJoinB, 0);

    int convBlocks = (n * 32 + 255) / 256;
    // kernel #6: conv1
    k_conv<0><<<convBlocks, 256>>>(nullptr, x1, nullptr, nullptr, n);
    // kernel #7: conv2 (+ fused lin2/log_softmax)
    k_conv<1><<<convBlocks, 256>>>(bet2, out, w2, b2, n);
}